// round 5
// baseline (speedup 1.0000x reference)
#include <cuda_runtime.h>
#include <cuda_bf16.h>
#include <cstdint>
#include <math.h>

#define NMAX 100000
#define EMAX 1600000
#define HDIM 64
#define LMAX 2
#define K1B 512   // B1 row: [hi(4x64) | lo(4x64)]
#define K2B 256   // B2 row: [hi(2x64) | lo(2x64)]

// ---------------- scratch (static device memory) ---------------------------
__device__ __align__(16) int   g_deg[NMAX];
__device__ __align__(16) int   g_rowptr[NMAX + 1];
__device__ __align__(16) int   g_cursor[NMAX];
__device__ __align__(16) int   g_csr[EMAX];
__device__ __align__(16) float g_invdeg[NMAX];
__device__ __align__(16) int   g_bsum[512];

__device__ __align__(16) float g_AGX[(size_t)NMAX * HDIM];  // mean-agg of x
__device__ __align__(16) float g_AGH[(size_t)NMAX * HDIM];  // mean-agg of h
__device__ __align__(16) float g_AG2[(size_t)NMAX * HDIM];  // mean-agg of r*h
__device__ __align__(16) float g_Z [(size_t)NMAX * HDIM];
__device__ __align__(16) float g_TP[(size_t)NMAX * HDIM];
__device__ __align__(16) float g_RH[(size_t)NMAX * HDIM];

__device__ __align__(16) __nv_bfloat16 g_Bt1[(size_t)LMAX * 192 * K1B];
__device__ __align__(16) __nv_bfloat16 g_Bt2[(size_t)LMAX * 64 * K2B];
__device__ __align__(16) float g_bias1[LMAX * 192];
__device__ __align__(16) float g_bias2[LMAX * 64];

// ---------------- helpers --------------------------------------------------
__device__ __forceinline__ float sigm(float x) { return 1.0f / (1.0f + __expf(-x)); }
__device__ __forceinline__ float fast_tanh(float x) {
    float xc = fminf(fmaxf(x, -30.0f), 30.0f);
    return 1.0f - __fdividef(2.0f, __expf(2.0f * xc) + 1.0f);
}

__device__ __forceinline__ void mma_bf16(float (&d)[4], const uint32_t (&a)[4],
                                         const uint32_t (&b)[2]) {
    asm volatile(
        "mma.sync.aligned.m16n8k16.row.col.f32.bf16.bf16.f32 "
        "{%0,%1,%2,%3}, {%4,%5,%6,%7}, {%8,%9}, {%0,%1,%2,%3};\n"
        : "+f"(d[0]), "+f"(d[1]), "+f"(d[2]), "+f"(d[3])
        : "r"(a[0]), "r"(a[1]), "r"(a[2]), "r"(a[3]), "r"(b[0]), "r"(b[1]));
}
__device__ __forceinline__ uint32_t sptr(const void* p) {
    return (uint32_t)__cvta_generic_to_shared(p);
}
__device__ __forceinline__ void ldsm_x4(uint32_t (&r)[4], uint32_t addr) {
    asm volatile("ldmatrix.sync.aligned.m8n8.x4.shared.b16 {%0,%1,%2,%3}, [%4];\n"
                 : "=r"(r[0]), "=r"(r[1]), "=r"(r[2]), "=r"(r[3]) : "r"(addr));
}
__device__ __forceinline__ void split_pack2(float a, float b, uint32_t& hi2, uint32_t& lo2) {
    __nv_bfloat16 ha = __float2bfloat16_rn(a), hb = __float2bfloat16_rn(b);
    __nv_bfloat16 la = __float2bfloat16_rn(a - __bfloat162float(ha));
    __nv_bfloat16 lb = __float2bfloat16_rn(b - __bfloat162float(hb));
    hi2 = ((uint32_t)__bfloat16_as_ushort(hb) << 16) | __bfloat16_as_ushort(ha);
    lo2 = ((uint32_t)__bfloat16_as_ushort(lb) << 16) | __bfloat16_as_ushort(la);
}

// ---------------- CSR build ------------------------------------------------
__global__ void k_zero_deg(int N) {
    int i = blockIdx.x * blockDim.x + threadIdx.x;
    if (i < N) g_deg[i] = 0;
}

// 4 edges per thread for MLP
__global__ void k_count(const int* __restrict__ edg, int E, int N) {
    int base = (blockIdx.x * blockDim.x + threadIdx.x) * 4;
    #pragma unroll
    for (int i = 0; i < 4; i++) {
        int e = base + i;
        if (e < E) {
            int dst = __ldg(edg + E + e);
            if ((unsigned)dst < (unsigned)N) atomicAdd(&g_deg[dst], 1);
        }
    }
}

// parallel 3-phase scan
__global__ void k_scan1(int N) {
    __shared__ int ws[8];
    int tid = threadIdx.x, lane = tid & 31, wid = tid >> 5;
    int i = blockIdx.x * 256 + tid;
    int v = (i < N) ? g_deg[i] : 0;
    int x = v;
    #pragma unroll
    for (int o = 1; o < 32; o <<= 1) x += __shfl_down_sync(0xffffffffu, x, o);
    if (lane == 0) ws[wid] = x;
    __syncthreads();
    if (tid == 0) {
        int s = 0;
        #pragma unroll
        for (int w = 0; w < 8; w++) s += ws[w];
        g_bsum[blockIdx.x] = s;
    }
}

__global__ void k_scan2(int nb, int N) {
    __shared__ int ws[16];
    int tid = threadIdx.x, lane = tid & 31, wid = tid >> 5;
    int v = (tid < nb) ? g_bsum[tid] : 0;
    int x = v;
    #pragma unroll
    for (int o = 1; o < 32; o <<= 1) {
        int y = __shfl_up_sync(0xffffffffu, x, o);
        if (lane >= o) x += y;
    }
    if (lane == 31) ws[wid] = x;
    __syncthreads();
    if (wid == 0 && lane < 16) {
        int w = ws[lane];
        #pragma unroll
        for (int o = 1; o < 16; o <<= 1) {
            int y = __shfl_up_sync(0xffffu, w, o);
            if (lane >= o) w += y;
        }
        ws[lane] = w;
    }
    __syncthreads();
    int excl = x - v + (wid > 0 ? ws[wid - 1] : 0);
    if (tid < nb) g_bsum[tid] = excl;
    if (tid == nb - 1) g_rowptr[N] = excl + v;
}

__global__ void k_scan3(int N) {
    __shared__ int ws[8];
    int tid = threadIdx.x, lane = tid & 31, wid = tid >> 5;
    int i = blockIdx.x * 256 + tid;
    int v = (i < N) ? g_deg[i] : 0;
    int x = v;
    #pragma unroll
    for (int o = 1; o < 32; o <<= 1) {
        int y = __shfl_up_sync(0xffffffffu, x, o);
        if (lane >= o) x += y;
    }
    if (lane == 31) ws[wid] = x;
    __syncthreads();
    if (wid == 0 && lane < 8) {
        int w = ws[lane];
        #pragma unroll
        for (int o = 1; o < 8; o <<= 1) {
            int y = __shfl_up_sync(0xffu, w, o);
            if (lane >= o) w += y;
        }
        ws[lane] = w;
    }
    __syncthreads();
    if (i < N) {
        int excl = x - v + (wid > 0 ? ws[wid - 1] : 0) + g_bsum[blockIdx.x];
        g_rowptr[i] = excl;
        g_cursor[i] = excl;
        g_invdeg[i] = (v > 0) ? 1.0f / (float)v : 0.0f;
    }
}

__global__ void k_scatter(const int* __restrict__ edg, int E, int N) {
    int base = (blockIdx.x * blockDim.x + threadIdx.x) * 4;
    #pragma unroll
    for (int i = 0; i < 4; i++) {
        int e = base + i;
        if (e < E) {
            int src = __ldg(edg + e);
            int dst = __ldg(edg + E + e);
            if ((unsigned)src < (unsigned)N && (unsigned)dst < (unsigned)N) {
                int pos = atomicAdd(&g_cursor[dst], 1);
                g_csr[pos] = src;
            }
        }
    }
}

// ---------------- weight / bias packing (single kernel) ---------------------
__global__ void k_packAll(const float* __restrict__ Wl, const float* __restrict__ b,
                          const float* __restrict__ Wr, int L) {
    int idx = blockIdx.x * blockDim.x + threadIdx.x;
    int t1 = L * 192 * K1B;
    int t2 = L * 64 * K2B;
    int t3 = L * 256;
    if (idx < t1) {
        // B1[l][j][k]: j=g*64+jj, k=t*256+s*64+c
        int k = idx % K1B;
        int j = (idx / K1B) % 192;
        int l = idx / (K1B * 192);
        int t = k / 256, rem = k % 256, s = rem / 64, c = rem % 64;
        int g = j / 64, jj = j % 64;
        int gbase = 2 * g;
        float w = 0.0f;
        if (s == 0)      w = Wl[(((size_t)l * 6 + gbase) * 64 + jj) * 64 + c];
        else if (s == 1) w = Wr[(((size_t)l * 6 + gbase) * 64 + jj) * 64 + c];
        else if (s == 2) { if (g < 2) w = Wl[(((size_t)l * 6 + gbase + 1) * 64 + jj) * 64 + c]; }
        else             { if (g < 2) w = Wr[(((size_t)l * 6 + gbase + 1) * 64 + jj) * 64 + c]; }
        __nv_bfloat16 hi = __float2bfloat16_rn(w);
        __nv_bfloat16 val = (t == 1) ? __float2bfloat16_rn(w - __bfloat162float(hi)) : hi;
        g_Bt1[(size_t)(l * 192 + j) * K1B + k] = val;
    } else if (idx < t1 + t2) {
        int i2 = idx - t1;
        int k = i2 % K2B;
        int j = (i2 / K2B) % 64;
        int l = i2 / (K2B * 64);
        int t = k / 128, rem = k % 128, s = rem / 64, c = rem % 64;
        const float* W = s ? Wr : Wl;
        float w = W[(((size_t)l * 6 + 5) * 64 + j) * 64 + c];
        __nv_bfloat16 hi = __float2bfloat16_rn(w);
        __nv_bfloat16 val = (t == 1) ? __float2bfloat16_rn(w - __bfloat162float(hi)) : hi;
        g_Bt2[(size_t)(l * 64 + j) * K2B + k] = val;
    } else if (idx < t1 + t2 + t3) {
        int i3 = idx - t1 - t2;
        int j = i3 % 256, l = i3 / 256;
        if (j < 192) {
            int g = j / 64, jj = j % 64;
            float v;
            if (g == 0)      v = b[((size_t)l * 6 + 0) * 64 + jj] + b[((size_t)l * 6 + 1) * 64 + jj];
            else if (g == 1) v = b[((size_t)l * 6 + 2) * 64 + jj] + b[((size_t)l * 6 + 3) * 64 + jj];
            else             v = b[((size_t)l * 6 + 4) * 64 + jj];
            g_bias1[l * 192 + j] = v;
        } else {
            int jj = j - 192;
            g_bias2[l * 64 + jj] = b[((size_t)l * 6 + 5) * 64 + jj];
        }
    }
}

// ---------------- aggregation: warp/node, half-warp per edge, float4 -------
__global__ void __launch_bounds__(512) k_agg1(const float* __restrict__ x,
                                              const float* __restrict__ h, int N) {
    int node = (blockIdx.x * blockDim.x + threadIdx.x) >> 5;
    if (node >= N) return;
    int lane = threadIdx.x & 31;
    int half = lane >> 4, hl = lane & 15;
    int beg = g_rowptr[node], end = g_rowptr[node + 1];
    float4 sx = make_float4(0.f, 0.f, 0.f, 0.f);
    float4 sh = make_float4(0.f, 0.f, 0.f, 0.f);
    int e = beg + half;
    // unroll 2 (each half-warp strides by 2 edges)
    for (; e + 2 < end; e += 4) {
        int s0 = g_csr[e], s1 = g_csr[e + 2];
        float4 a0 = __ldg((const float4*)(x + (size_t)s0 * HDIM) + hl);
        float4 b0 = __ldg((const float4*)(h + (size_t)s0 * HDIM) + hl);
        float4 a1 = __ldg((const float4*)(x + (size_t)s1 * HDIM) + hl);
        float4 b1 = __ldg((const float4*)(h + (size_t)s1 * HDIM) + hl);
        sx.x += a0.x + a1.x; sx.y += a0.y + a1.y; sx.z += a0.z + a1.z; sx.w += a0.w + a1.w;
        sh.x += b0.x + b1.x; sh.y += b0.y + b1.y; sh.z += b0.z + b1.z; sh.w += b0.w + b1.w;
    }
    if (e < end) {
        int s0 = g_csr[e];
        float4 a0 = __ldg((const float4*)(x + (size_t)s0 * HDIM) + hl);
        float4 b0 = __ldg((const float4*)(h + (size_t)s0 * HDIM) + hl);
        sx.x += a0.x; sx.y += a0.y; sx.z += a0.z; sx.w += a0.w;
        sh.x += b0.x; sh.y += b0.y; sh.z += b0.z; sh.w += b0.w;
    }
    // combine even/odd halves (same columns in both halves)
    sx.x += __shfl_xor_sync(0xffffffffu, sx.x, 16);
    sx.y += __shfl_xor_sync(0xffffffffu, sx.y, 16);
    sx.z += __shfl_xor_sync(0xffffffffu, sx.z, 16);
    sx.w += __shfl_xor_sync(0xffffffffu, sx.w, 16);
    sh.x += __shfl_xor_sync(0xffffffffu, sh.x, 16);
    sh.y += __shfl_xor_sync(0xffffffffu, sh.y, 16);
    sh.z += __shfl_xor_sync(0xffffffffu, sh.z, 16);
    sh.w += __shfl_xor_sync(0xffffffffu, sh.w, 16);
    float inv = g_invdeg[node];
    size_t o = (size_t)node * HDIM;
    if (half == 0) {
        float4 v = make_float4(sx.x * inv, sx.y * inv, sx.z * inv, sx.w * inv);
        ((float4*)(g_AGX + o))[hl] = v;
    } else {
        float4 v = make_float4(sh.x * inv, sh.y * inv, sh.z * inv, sh.w * inv);
        ((float4*)(g_AGH + o))[hl] = v;
    }
}

__global__ void __launch_bounds__(512) k_agg2(int N) {
    int node = (blockIdx.x * blockDim.x + threadIdx.x) >> 5;
    if (node >= N) return;
    int lane = threadIdx.x & 31;
    int half = lane >> 4, hl = lane & 15;
    int beg = g_rowptr[node], end = g_rowptr[node + 1];
    float4 s = make_float4(0.f, 0.f, 0.f, 0.f);
    int e = beg + half;
    for (; e + 2 < end; e += 4) {
        int s0 = g_csr[e], s1 = g_csr[e + 2];
        float4 a0 = __ldg((const float4*)(g_RH + (size_t)s0 * HDIM) + hl);
        float4 a1 = __ldg((const float4*)(g_RH + (size_t)s1 * HDIM) + hl);
        s.x += a0.x + a1.x; s.y += a0.y + a1.y; s.z += a0.z + a1.z; s.w += a0.w + a1.w;
    }
    if (e < end) {
        int s0 = g_csr[e];
        float4 a0 = __ldg((const float4*)(g_RH + (size_t)s0 * HDIM) + hl);
        s.x += a0.x; s.y += a0.y; s.z += a0.z; s.w += a0.w;
    }
    s.x += __shfl_xor_sync(0xffffffffu, s.x, 16);
    s.y += __shfl_xor_sync(0xffffffffu, s.y, 16);
    s.z += __shfl_xor_sync(0xffffffffu, s.z, 16);
    s.w += __shfl_xor_sync(0xffffffffu, s.w, 16);
    if (half == 0) {
        float inv = g_invdeg[node];
        float4 v = make_float4(s.x * inv, s.y * inv, s.z * inv, s.w * inv);
        ((float4*)(g_AG2 + (size_t)node * HDIM))[hl] = v;
    }
}

// ---------------- GEMM 1: all gates fused, f32 sources, inline split -------
// 512 threads, 16 warps (4M x 4N), BM=128, BN=192, warp tile 32x48
#define BM 128
#define SMPAD 72
#define G1_ASHI 0
#define G1_ASLO (128 * SMPAD)
#define G1_BSHI (2 * 128 * SMPAD)
#define G1_BSLO (2 * 128 * SMPAD + 192 * SMPAD)
#define GEMM1_SMEM ((2 * 128 * SMPAD + 2 * 192 * SMPAD) * 2)

__global__ void __launch_bounds__(512) k_gemm1(int N, int l,
                                               const float* __restrict__ xptr,
                                               const float* __restrict__ hptr) {
    extern __shared__ __nv_bfloat16 sm[];
    __nv_bfloat16* AsHi = sm + G1_ASHI;
    __nv_bfloat16* AsLo = sm + G1_ASLO;
    __nv_bfloat16* BsHi = sm + G1_BSHI;
    __nv_bfloat16* BsLo = sm + G1_BSLO;

    int n0 = blockIdx.x * BM;
    int tid = threadIdx.x;
    int wid = tid >> 5, lane = tid & 31;
    int warpM = wid >> 2, warpN = wid & 3;

    float acc[2][6][4];
    #pragma unroll
    for (int mt = 0; mt < 2; mt++)
        #pragma unroll
        for (int nt = 0; nt < 6; nt++)
            #pragma unroll
            for (int q = 0; q < 4; q++) acc[mt][nt][q] = 0.f;

    const __nv_bfloat16* Bg = g_Bt1 + (size_t)l * 192 * K1B;

    #pragma unroll 1
    for (int s = 0; s < 4; s++) {
        const float* S = (s == 0) ? g_AGX : (s == 1) ? xptr : (s == 2) ? g_AGH : hptr;
        #pragma unroll
        for (int i = 0; i < 4; i++) {
            int idx = tid + i * 512;
            int r = idx >> 4, q4 = idx & 15;
            float4 v = make_float4(0.f, 0.f, 0.f, 0.f);
            if (n0 + r < N)
                v = *(const float4*)(S + (size_t)(n0 + r) * HDIM + q4 * 4);
            uint32_t h0, l0, h1, l1;
            split_pack2(v.x, v.y, h0, l0);
            split_pack2(v.z, v.w, h1, l1);
            *(uint2*)(AsHi + r * SMPAD + q4 * 4) = make_uint2(h0, h1);
            *(uint2*)(AsLo + r * SMPAD + q4 * 4) = make_uint2(l0, l1);
        }
        #pragma unroll
        for (int i = 0; i < 3; i++) {
            int idx = tid + i * 512;
            int j = idx >> 3, c8 = idx & 7;
            *(int4*)(BsHi + j * SMPAD + c8 * 8) =
                *(const int4*)(Bg + (size_t)j * K1B + s * 64 + c8 * 8);
            *(int4*)(BsLo + j * SMPAD + c8 * 8) =
                *(const int4*)(Bg + (size_t)j * K1B + 256 + s * 64 + c8 * 8);
        }
        __syncthreads();
        #pragma unroll
        for (int ks = 0; ks < 4; ks++) {
            int cc = ks * 16;
            uint32_t ah[2][4], al[2][4];
            #pragma unroll
            for (int mt = 0; mt < 2; mt++) {
                int row = warpM * 32 + mt * 16 + (lane & 15);
                int col = cc + ((lane >> 4) << 3);
                ldsm_x4(ah[mt], sptr(AsHi + row * SMPAD + col));
                ldsm_x4(al[mt], sptr(AsLo + row * SMPAD + col));
            }
            uint32_t bh[6][2], bl[6][2];
            #pragma unroll
            for (int pr = 0; pr < 3; pr++) {
                int j = warpN * 48 + pr * 16 + ((lane >> 4) << 3) + (lane & 7);
                int col = cc + (((lane >> 3) & 1) << 3);
                uint32_t t4[4];
                ldsm_x4(t4, sptr(BsHi + j * SMPAD + col));
                bh[pr * 2][0] = t4[0]; bh[pr * 2][1] = t4[1];
                bh[pr * 2 + 1][0] = t4[2]; bh[pr * 2 + 1][1] = t4[3];
                ldsm_x4(t4, sptr(BsLo + j * SMPAD + col));
                bl[pr * 2][0] = t4[0]; bl[pr * 2][1] = t4[1];
                bl[pr * 2 + 1][0] = t4[2]; bl[pr * 2 + 1][1] = t4[3];
            }
            #pragma unroll
            for (int mt = 0; mt < 2; mt++)
                #pragma unroll
                for (int nt = 0; nt < 6; nt++) {
                    mma_bf16(acc[mt][nt], ah[mt], bh[nt]);
                    mma_bf16(acc[mt][nt], ah[mt], bl[nt]);
                    mma_bf16(acc[mt][nt], al[mt], bh[nt]);
                }
        }
        __syncthreads();
    }

    // fused epilogue: z | r -> rh | t-partial
    #pragma unroll
    for (int mt = 0; mt < 2; mt++) {
        int r0 = n0 + warpM * 32 + mt * 16 + (lane >> 2);
        #pragma unroll
        for (int nt = 0; nt < 6; nt++) {
            int jc0 = warpN * 48 + nt * 8 + (lane & 3) * 2;
            #pragma unroll
            for (int q = 0; q < 4; q++) {
                int row = r0 + ((q >> 1) << 3);
                int jc  = jc0 + (q & 1);
                if (row < N) {
                    float v = acc[mt][nt][q] + g_bias1[l * 192 + jc];
                    int jj = jc & 63;
                    size_t o = (size_t)row * HDIM + jj;
                    if (jc < 64) {
                        g_Z[o] = sigm(v);
                    } else if (jc < 128) {
                        float r = sigm(v);
                        g_RH[o] = r * hptr[o];
                    } else {
                        g_TP[o] = v;
                    }
                }
            }
        }
    }
}

// ---------------- GEMM 2: gate 5 + final GRU combine -----------------------
#define G2_ASHI 0
#define G2_ASLO (128 * SMPAD)
#define G2_BSHI (2 * 128 * SMPAD)
#define G2_BSLO (2 * 128 * SMPAD + 64 * SMPAD)
#define GEMM2_SMEM ((2 * 128 * SMPAD + 2 * 64 * SMPAD) * 2)

__global__ void __launch_bounds__(256) k_gemm2(int N, int l,
                                               const float* __restrict__ hptr,
                                               float* __restrict__ out) {
    extern __shared__ __nv_bfloat16 sm[];
    __nv_bfloat16* AsHi = sm + G2_ASHI;
    __nv_bfloat16* AsLo = sm + G2_ASLO;
    __nv_bfloat16* BsHi = sm + G2_BSHI;
    __nv_bfloat16* BsLo = sm + G2_BSLO;

    int n0 = blockIdx.x * BM;
    int tid = threadIdx.x;
    int wid = tid >> 5, lane = tid & 31;
    int warpM = wid >> 1, warpN = wid & 1;

    float acc[2][4][4];
    #pragma unroll
    for (int mt = 0; mt < 2; mt++)
        #pragma unroll
        for (int nt = 0; nt < 4; nt++)
            #pragma unroll
            for (int q = 0; q < 4; q++) acc[mt][nt][q] = 0.f;

    const __nv_bfloat16* Bg = g_Bt2 + (size_t)l * 64 * K2B;

    #pragma unroll 1
    for (int s = 0; s < 2; s++) {
        const float* S = (s == 0) ? g_AG2 : g_RH;
        #pragma unroll
        for (int i = 0; i < 8; i++) {
            int idx = tid + i * 256;
            int r = idx >> 4, q4 = idx & 15;
            float4 v = make_float4(0.f, 0.f, 0.f, 0.f);
            if (n0 + r < N)
                v = *(const float4*)(S + (size_t)(n0 + r) * HDIM + q4 * 4);
            uint32_t h0, l0, h1, l1;
            split_pack2(v.x, v.y, h0, l0);
            split_pack2(v.z, v.w, h1, l1);
            *(uint2*)(AsHi + r * SMPAD + q4 * 4) = make_uint2(h0, h1);
            *(uint2*)(AsLo + r * SMPAD + q4 * 4) = make_uint2(l0, l1);
        }
        #pragma unroll
        for (int i = 0; i < 2; i++) {
            int idx = tid + i * 256;
            int j = idx >> 3, c8 = idx & 7;
            *(int4*)(BsHi + j * SMPAD + c8 * 8) =
                *(const int4*)(Bg + (size_t)j * K2B + s * 64 + c8 * 8);
            *(int4*)(BsLo + j * SMPAD + c8 * 8) =
                *(const int4*)(Bg + (size_t)j * K2B + 128 + s * 64 + c8 * 8);
        }
        __syncthreads();
        #pragma unroll
        for (int ks = 0; ks < 4; ks++) {
            int cc = ks * 16;
            uint32_t ah[2][4], al[2][4];
            #pragma unroll
            for (int mt = 0; mt < 2; mt++) {
                int row = warpM * 32 + mt * 16 + (lane & 15);
                int col = cc + ((lane >> 4) << 3);
                ldsm_x4(ah[mt], sptr(AsHi + row * SMPAD + col));
                ldsm_x4(al[mt], sptr(AsLo + row * SMPAD + col));
            }
            uint32_t bh[4][2], bl[4][2];
            #pragma unroll
            for (int pr = 0; pr < 2; pr++) {
                int j = warpN * 32 + pr * 16 + ((lane >> 4) << 3) + (lane & 7);
                int col = cc + (((lane >> 3) & 1) << 3);
                uint32_t t4[4];
                ldsm_x4(t4, sptr(BsHi + j * SMPAD + col));
                bh[pr * 2][0] = t4[0]; bh[pr * 2][1] = t4[1];
                bh[pr * 2 + 1][0] = t4[2]; bh[pr * 2 + 1][1] = t4[3];
                ldsm_x4(t4, sptr(BsLo + j * SMPAD + col));
                bl[pr * 2][0] = t4[0]; bl[pr * 2][1] = t4[1];
                bl[pr * 2 + 1][0] = t4[2]; bl[pr * 2 + 1][1] = t4[3];
            }
            #pragma unroll
            for (int mt = 0; mt < 2; mt++)
                #pragma unroll
                for (int nt = 0; nt < 4; nt++) {
                    mma_bf16(acc[mt][nt], ah[mt], bh[nt]);
                    mma_bf16(acc[mt][nt], ah[mt], bl[nt]);
                    mma_bf16(acc[mt][nt], al[mt], bh[nt]);
                }
        }
        __syncthreads();
    }

    #pragma unroll
    for (int mt = 0; mt < 2; mt++) {
        int r0 = n0 + warpM * 32 + mt * 16 + (lane >> 2);
        #pragma unroll
        for (int nt = 0; nt < 4; nt++) {
            int jc0 = warpN * 32 + nt * 8 + (lane & 3) * 2;
            #pragma unroll
            for (int q = 0; q < 4; q++) {
                int row = r0 + ((q >> 1) << 3);
                int jc  = jc0 + (q & 1);
                if (row < N) {
                    size_t o = (size_t)row * HDIM + jc;
                    float v = acc[mt][nt][q] + g_bias2[l * 64 + jc] + g_TP[o];
                    float t = fast_tanh(v);
                    float z = g_Z[o];
                    float hv = hptr[o];
                    out[(size_t)l * N * HDIM + o] = z * hv + (1.0f - z) * t;
                }
            }
        }
    }
}

// ---------------- launch ----------------------------------------------------
extern "C" void kernel_launch(void* const* d_in, const int* in_sizes, int n_in,
                              void* d_out, int out_size) {
    const float* inp = (const float*)d_in[0];
    const int*   edg = (const int*)d_in[1];   // int64 in reference -> int32 in harness
    const float* h   = (const float*)d_in[2];
    const float* Wl  = (const float*)d_in[3];
    const float* b   = (const float*)d_in[4];
    const float* Wr  = (const float*)d_in[5];
    float* out = (float*)d_out;

    int N = in_sizes[0] / HDIM;
    int E = in_sizes[1] / 2;
    int L = in_sizes[2] / in_sizes[0];
    if (N > NMAX || E > EMAX || L > LMAX) return;

    cudaFuncSetAttribute(k_gemm1, cudaFuncAttributeMaxDynamicSharedMemorySize, GEMM1_SMEM);
    cudaFuncSetAttribute(k_gemm2, cudaFuncAttributeMaxDynamicSharedMemorySize, GEMM2_SMEM);

    int scanBlocks = (N + 255) / 256;

    // CSR build
    k_zero_deg<<<(N + 255) / 256, 256>>>(N);
    k_count<<<(E + 1023) / 1024, 256>>>(edg, E, N);
    k_scan1<<<scanBlocks, 256>>>(N);
    k_scan2<<<1, 512>>>(scanBlocks, N);
    k_scan3<<<scanBlocks, 256>>>(N);
    k_scatter<<<(E + 1023) / 1024, 256>>>(edg, E, N);

    // weight + bias packing (single kernel)
    int packTotal = L * 192 * K1B + L * 64 * K2B + L * 256;
    k_packAll<<<(packTotal + 255) / 256, 256>>>(Wl, b, Wr, L);

    int aggBlocks = (N * 32 + 511) / 512;
    int rowTiles  = (N + BM - 1) / BM;

    const float* x = inp;
    for (int l = 0; l < L; l++) {
        const float* hl = h + (size_t)l * N * HDIM;
        k_agg1<<<aggBlocks, 512>>>(x, hl, N);
        k_gemm1<<<rowTiles, 512, GEMM1_SMEM>>>(N, l, x, hl);
        k_agg2<<<aggBlocks, 512>>>(N);
        k_gemm2<<<rowTiles, 256, GEMM2_SMEM>>>(N, l, hl, out);
        x = out + (size_t)l * N * HDIM;
    }
}